// round 8
// baseline (speedup 1.0000x reference)
#include <cuda_runtime.h>

// LengthRegulator: out[b, t, :] = x[b, j, :] where token j owns frame t
// (cum[j-1] <= t < cum[j]); zero for t >= cum[L-1]. Second output: durations
// echoed back as float. Shapes: N=16, L=512, D=384, T=3584.
//
// Token-major, 4 tokens per 96-lane group (load MLP=4), default write-back
// stores (output fits in L2 -> steady-state replays stay L2-resident).

#define NB 16
#define LL 512
#define DD 384
#define V4 (DD / 4)                 // 96 float4 per frame
#define GROUPS 4                    // token groups per block (96 lanes each)
#define TPG 4                       // tokens per group
#define THREADS (V4 * GROUPS)       // 384
#define DATA_BLKS (LL / (GROUPS * TPG))  // 32 blocks cover 512 tokens
#define ZTILE 32                    // frames per zero-fill block

// Scratch (allocation-free rule: __device__ globals).
__device__ int g_cum[NB * LL];      // inclusive cumsum of durations

// ---------------------------------------------------------------------------
// Kernel 1: prep. 16 blocks x 512 threads: block scan + echo durations.
// ---------------------------------------------------------------------------
__global__ void lr_prep_kernel(const int* __restrict__ dur,
                               float* __restrict__ echo_dst) {
    __shared__ int warp_sums[16];
    const int b = blockIdx.x;
    const int j = threadIdx.x;
    const int lane = j & 31;
    const int w = j >> 5;

    const int d = dur[b * LL + j];

    int inc = d;
#pragma unroll
    for (int off = 1; off < 32; off <<= 1) {
        int v = __shfl_up_sync(0xffffffffu, inc, off);
        if (lane >= off) inc += v;
    }
    if (lane == 31) warp_sums[w] = inc;
    __syncthreads();

    if (w == 0) {
        int s = warp_sums[lane & 15];
#pragma unroll
        for (int off = 1; off < 16; off <<= 1) {
            int v = __shfl_up_sync(0xffffffffu, s, off);
            if ((lane & 15) >= off) s += v;
        }
        if (lane < 16) warp_sums[lane] = s;
    }
    __syncthreads();

    const int c = inc + (w > 0 ? warp_sums[w - 1] : 0);
    g_cum[b * LL + j] = c;

    if (echo_dst) echo_dst[b * LL + j] = (float)d;
}

// ---------------------------------------------------------------------------
// Kernel 2: token-major write (4 tokens/group) + zero tail.
// grid = (DATA_BLKS + T/ZTILE, N), block = 384 (4 groups x 96 lanes).
//  bx <  DATA_BLKS : group g handles tokens j0..j0+3, j0=(bx*4+g)*4:
//                    one int4 cum load + one int4 dur load + 4 independent
//                    float4 row gathers, then coalesced write-back stores.
//  bx >= DATA_BLKS : zero-fill frames in [total, T).
// ---------------------------------------------------------------------------
__global__ void __launch_bounds__(THREADS)
lr_write_kernel(const float* __restrict__ x,
                const int* __restrict__ dur,
                float* __restrict__ out, int T) {
    const int b = blockIdx.y;
    const int tid = threadIdx.x;
    const int g = tid / V4;          // 0..3
    const int v = tid % V4;          // 0..95
    const int bx = blockIdx.x;

    if (bx < DATA_BLKS) {
        const int j0 = (bx * GROUPS + g) * TPG;

        // warp-uniform 16B metadata loads
        const int4 c4 = *reinterpret_cast<const int4*>(&g_cum[b * LL + j0]);
        const int4 d4 = *reinterpret_cast<const int4*>(&dur[b * LL + j0]);
        const int cs[TPG] = {c4.x, c4.y, c4.z, c4.w};
        const int ds[TPG] = {d4.x, d4.y, d4.z, d4.w};

        const float4* xb = reinterpret_cast<const float4*>(
                               x + ((size_t)b * LL + j0) * DD);

        // 4 independent row gathers (MLP=4)
        float4 val[TPG];
#pragma unroll
        for (int k = 0; k < TPG; ++k)
            val[k] = __ldg(xb + (size_t)k * V4 + v);

        float4* ob = reinterpret_cast<float4*>(out + (size_t)b * T * DD);
#pragma unroll
        for (int k = 0; k < TPG; ++k) {
            const int d = ds[k];
            const int start = cs[k] - d;
#pragma unroll 7
            for (int i = 0; i < d; ++i)
                ob[(size_t)(start + i) * V4 + v] = val[k];
        }
    } else {
        const int z = bx - DATA_BLKS;
        const int total = __ldg(&g_cum[b * LL + (LL - 1)]);
        const int t0 = z * ZTILE;
        if (t0 + ZTILE <= total) return;     // fully inside data region

        const float4 zero = make_float4(0.f, 0.f, 0.f, 0.f);
        float4* ob = reinterpret_cast<float4*>(out + (size_t)b * T * DD);
#pragma unroll
        for (int k = 0; k < ZTILE / GROUPS; ++k) {
            const int t = t0 + g + k * GROUPS;
            if (t >= total)
                ob[(size_t)t * V4 + v] = zero;
        }
    }
}

extern "C" void kernel_launch(void* const* d_in, const int* in_sizes, int n_in,
                              void* d_out, int out_size) {
    const float* x = (const float*)d_in[0];
    const int* dur = (const int*)d_in[1];

    const int NL = NB * LL;                          // 8192
    const long long per_frame = (long long)NB * DD;  // 6144 elems per time step

    long long main_elems = out_size;
    float* echo_dst = nullptr;
    if (main_elems % per_frame != 0) {
        main_elems -= NL;
        echo_dst = (float*)d_out + main_elems;
    }
    const int T = (int)(main_elems / per_frame);     // 3584

    lr_prep_kernel<<<NB, LL>>>(dur, echo_dst);

    dim3 grid(DATA_BLKS + T / ZTILE, NB);            // (32+112) x 16
    lr_write_kernel<<<grid, THREADS>>>(x, dur, (float*)d_out, T);
}